// round 6
// baseline (speedup 1.0000x reference)
#include <cuda_runtime.h>
#include <cstdint>
#include <cmath>

#define B_SZ   64
#define KCP    16
#define NDIM   19            // K + 3
#define NPAD   20            // padded coeff entries (affine at 16..18, pad 19)
#define HH     512
#define WW     512
#define HWPIX  (HH * WW)
#define PAIRS  (HWPIX / 2)   // 131072 pixel pairs

// inv_delta[:, :16] passed by value (computed on host — input-independent).
struct InvW {
    float w[NDIM][KCP];
};

// ---------------------------------------------------------------------------
// Packed f32x2 helpers (sm_103a).
// ---------------------------------------------------------------------------
__device__ __forceinline__ unsigned long long pack2(float lo, float hi) {
    unsigned long long r;
    asm("mov.b64 %0, {%1, %2};" : "=l"(r) : "f"(lo), "f"(hi));
    return r;
}
__device__ __forceinline__ unsigned long long fma2(unsigned long long a,
                                                   unsigned long long b,
                                                   unsigned long long c) {
    unsigned long long d;
    asm("fma.rn.f32x2 %0, %1, %2, %3;" : "=l"(d) : "l"(a), "l"(b), "l"(c));
    return d;
}
// Sum of the two f32 lanes of a packed register pair.
__device__ __forceinline__ float lanesum(unsigned long long a) {
    float lo, hi;
    asm("mov.b64 {%0, %1}, %2;" : "=f"(lo), "=f"(hi) : "l"(a));
    return lo + hi;
}

// ---------------------------------------------------------------------------
// Fused kernel: every block (redundantly) computes the per-batch coefficients
// from sp (trivial: 39K FMA per block), then processes 256 pixel pairs
// against all 64 batches.
//
// Basis packing is along K: u[j] = (v[2j], v[2j+1]) — NOT lane-duplicated, so
// the 2-pixel basis is 40 regs (vs 64 duplicated) and is shared across both
// output dims. Coeffs are stored as separate x / y arrays of 20 floats so one
// LDS.128 delivers 4 consecutive K-coeffs for one dim.
// ---------------------------------------------------------------------------
__global__ void __launch_bounds__(256, 4) tps_fused_kernel(
    InvW inv, const float* __restrict__ sp, float4* __restrict__ out) {

    __shared__ __align__(16) float s_cx[B_SZ][NPAD];   // 5 KB
    __shared__ __align__(16) float s_cy[B_SZ][NPAD];   // 5 KB
    __shared__ float s_sp[B_SZ * KCP * 2];             // 8 KB

    const int tid = threadIdx.x;

    // Stage source points (2048 floats) into shared.
    {
        const float4* sp4 = reinterpret_cast<const float4*>(sp);
        float4* dst = reinterpret_cast<float4*>(s_sp);
        for (int i = tid; i < (B_SZ * KCP * 2) / 4; i += 256) dst[i] = sp4[i];
    }
    __syncthreads();

    // coeff[b][i][d] = sum_{j<16} invW[i][j] * sp[b][j][d]
    for (int t = tid; t < B_SZ * NDIM; t += 256) {
        const int b = t / NDIM, i = t - b * NDIM;
        const float* spb = s_sp + b * (KCP * 2);
        float ax = 0.0f, ay = 0.0f;
        #pragma unroll
        for (int j = 0; j < KCP; j++) {
            const float w = inv.w[i][j];
            ax = fmaf(w, spb[2 * j + 0], ax);
            ay = fmaf(w, spb[2 * j + 1], ay);
        }
        s_cx[b][i] = ax;
        s_cy[b][i] = ay;
    }
    for (int b = tid; b < B_SZ; b += 256) {
        s_cx[b][NDIM] = 0.0f;
        s_cy[b][NDIM] = 0.0f;
    }
    __syncthreads();

    // ---- per-thread pixel pair ----
    const int t  = blockIdx.x * 256 + tid;
    const int n0 = t * 2;
    const int w0 = n0 & (WW - 1);
    const int h  = n0 >> 9;
    const float X0 = fmaf((float)w0, 2.0f / (float)(WW - 1), -1.0f);
    const float X1 = X0 + 2.0f / (float)(WW - 1);
    const float Y  = fmaf((float)h, 2.0f / (float)(HH - 1), -1.0f);

    // Basis values v[0..19] for each pixel: 16 RBF terms, then 1, X, Y, 0.
    float v0[NPAD], v1[NPAD];
    #pragma unroll
    for (int k = 0; k < KCP; k++) {
        const float cx = -1.0f + (float)(k >> 2) * (2.0f / 3.0f);
        const float cy = -1.0f + (float)(k & 3) * (2.0f / 3.0f);
        const float dy  = Y - cy;
        const float dy2 = dy * dy;
        float dxa = X0 - cx;
        float r2a = fmaf(dxa, dxa, dy2);
        v0[k] = r2a * __logf(r2a + 1e-6f);
        float dxb = X1 - cx;
        float r2b = fmaf(dxb, dxb, dy2);
        v1[k] = r2b * __logf(r2b + 1e-6f);
    }
    v0[16] = 1.0f;  v0[17] = X0;  v0[18] = Y;  v0[19] = 0.0f;
    v1[16] = 1.0f;  v1[17] = X1;  v1[18] = Y;  v1[19] = 0.0f;

    // Pack along K: u[j] = (v[2j], v[2j+1]).  10 ull per pixel = 40 regs total.
    unsigned long long u0[NPAD / 2], u1[NPAD / 2];
    #pragma unroll
    for (int j = 0; j < NPAD / 2; j++) {
        u0[j] = pack2(v0[2 * j], v0[2 * j + 1]);
        u1[j] = pack2(v1[2 * j], v1[2 * j + 1]);
    }

    #pragma unroll 2
    for (int b = 0; b < B_SZ; b++) {
        const ulonglong2* cxp = reinterpret_cast<const ulonglong2*>(s_cx[b]);
        const ulonglong2* cyp = reinterpret_cast<const ulonglong2*>(s_cy[b]);
        unsigned long long ax0 = 0ULL, ay0 = 0ULL, ax1 = 0ULL, ay1 = 0ULL;
        #pragma unroll
        for (int m = 0; m < 5; m++) {
            const ulonglong2 qx = cxp[m];          // K-coeffs 4m..4m+3, x-dim
            const ulonglong2 qy = cyp[m];          // K-coeffs 4m..4m+3, y-dim
            ax0 = fma2(u0[2 * m + 0], qx.x, ax0);
            ax0 = fma2(u0[2 * m + 1], qx.y, ax0);
            ay0 = fma2(u0[2 * m + 0], qy.x, ay0);
            ay0 = fma2(u0[2 * m + 1], qy.y, ay0);
            ax1 = fma2(u1[2 * m + 0], qx.x, ax1);
            ax1 = fma2(u1[2 * m + 1], qx.y, ax1);
            ay1 = fma2(u1[2 * m + 0], qy.x, ay1);
            ay1 = fma2(u1[2 * m + 1], qy.y, ay1);
        }
        float4 r;
        r.x = lanesum(ax0);
        r.y = lanesum(ay0);
        r.z = lanesum(ax1);
        r.w = lanesum(ay1);
        out[(size_t)b * PAIRS + t] = r;            // STG.128
    }
}

// ---------------------------------------------------------------------------
// Host: build delta(19x19), invert (Gauss-Jordan, partial pivoting, fp64).
// Input-independent -> runs on CPU at capture time; rides in as kernel param.
// ---------------------------------------------------------------------------
static inline double h_cpx(int k) { return -1.0 + (double)(k >> 2) * (2.0 / 3.0); }
static inline double h_cpy(int k) { return -1.0 + (double)(k & 3) * (2.0 / 3.0); }

static void build_invw(InvW* out) {
    double M[NDIM][2 * NDIM];
    for (int r = 0; r < NDIM; r++)
        for (int c = 0; c < 2 * NDIM; c++) {
            double v = 0.0;
            if (c >= NDIM) {
                v = (c - NDIM == r) ? 1.0 : 0.0;
            } else if (r < KCP && c < KCP) {
                double dx = h_cpx(r) - h_cpx(c);
                double dy = h_cpy(r) - h_cpy(c);
                double r2 = dx * dx + dy * dy;
                v = r2 * log(r2 + 1e-6);
            } else if (r < KCP) {
                v = (c == KCP) ? 1.0 : ((c == KCP + 1) ? h_cpx(r) : h_cpy(r));
            } else if (c < KCP) {
                v = (r == KCP) ? 1.0 : ((r == KCP + 1) ? h_cpx(c) : h_cpy(c));
            }
            M[r][c] = v;
        }

    for (int p = 0; p < NDIM; p++) {
        int best = p;
        double bm = fabs(M[p][p]);
        for (int r = p + 1; r < NDIM; r++) {
            double m = fabs(M[r][p]);
            if (m > bm) { bm = m; best = r; }
        }
        if (best != p)
            for (int c = 0; c < 2 * NDIM; c++) {
                double tv = M[p][c]; M[p][c] = M[best][c]; M[best][c] = tv;
            }
        const double inv = 1.0 / M[p][p];
        for (int c = 0; c < 2 * NDIM; c++) M[p][c] *= inv;
        for (int r = 0; r < NDIM; r++) {
            if (r == p) continue;
            const double f = M[r][p];
            if (f == 0.0) continue;
            for (int c = 0; c < 2 * NDIM; c++) M[r][c] -= f * M[p][c];
        }
    }

    for (int i = 0; i < NDIM; i++)
        for (int j = 0; j < KCP; j++)
            out->w[i][j] = (float)M[i][NDIM + j];
}

// ---------------------------------------------------------------------------
extern "C" void kernel_launch(void* const* d_in, const int* in_sizes, int n_in,
                              void* d_out, int out_size) {
    const float* sp = (const float*)d_in[0];        // [64, 16, 2] fp32
    float4* out = (float4*)d_out;                   // [64, 512, 512, 2] fp32

    InvW inv;
    build_invw(&inv);                               // host-side, capture-time only

    tps_fused_kernel<<<PAIRS / 256, 256>>>(inv, sp, out);
}